// round 1
// baseline (speedup 1.0000x reference)
#include <cuda_runtime.h>

#define NU 200000
#define NI 100000
#define NN 300000
#define ED 64
#define NE 1000000
#define NE2 2000000
#define SCAN_B 1024
#define NBLK ((NN + SCAN_B - 1) / SCAN_B)   // 293

// Scratch (device globals — no allocation allowed)
__device__ int   g_deg[NN];
__device__ int   g_rowptr[NN + 1];
__device__ int   g_cursor[NN];
__device__ int   g_adj[NE2];
__device__ float g_dinv[NN];
__device__ float g_embA[NN * ED];
__device__ float g_embB[NN * ED];
__device__ int   g_part[512];

__global__ void k_zero() {
    int i = blockIdx.x * blockDim.x + threadIdx.x;
    if (i < NN) g_deg[i] = 0;
}

__global__ void k_count(const int* __restrict__ uid, const int* __restrict__ iid) {
    int e = blockIdx.x * blockDim.x + threadIdx.x;
    if (e < NE) {
        atomicAdd(&g_deg[uid[e]], 1);
        atomicAdd(&g_deg[NU + iid[e]], 1);
    }
}

// Block-local exclusive scan of degrees; block totals to g_part.
__global__ void k_scan1() {
    __shared__ int s[SCAN_B];
    int i = blockIdx.x * SCAN_B + threadIdx.x;
    int v = (i < NN) ? g_deg[i] : 0;
    s[threadIdx.x] = v;
    __syncthreads();
    for (int off = 1; off < SCAN_B; off <<= 1) {
        int t = (threadIdx.x >= off) ? s[threadIdx.x - off] : 0;
        __syncthreads();
        s[threadIdx.x] += t;
        __syncthreads();
    }
    if (i < NN) g_rowptr[i] = s[threadIdx.x] - v;   // exclusive within block
    if (threadIdx.x == SCAN_B - 1) g_part[blockIdx.x] = s[SCAN_B - 1];
}

// Single-block exclusive scan of the 293 block totals.
__global__ void k_scan2() {
    __shared__ int s[512];
    int v = (threadIdx.x < NBLK) ? g_part[threadIdx.x] : 0;
    s[threadIdx.x] = v;
    __syncthreads();
    for (int off = 1; off < 512; off <<= 1) {
        int t = (threadIdx.x >= off) ? s[threadIdx.x - off] : 0;
        __syncthreads();
        s[threadIdx.x] += t;
        __syncthreads();
    }
    if (threadIdx.x < NBLK) g_part[threadIdx.x] = s[threadIdx.x] - v;  // exclusive
}

// Add block offsets; init cursor + dinv.
__global__ void k_scan3() {
    int i = blockIdx.x * SCAN_B + threadIdx.x;
    if (i < NN) {
        int r = g_rowptr[i] + g_part[blockIdx.x];
        g_rowptr[i] = r;
        g_cursor[i] = r;
        int d = g_deg[i];
        g_dinv[i] = (d > 0) ? rsqrtf((float)d) : 0.0f;
    }
    if (i == 0) g_rowptr[NN] = NE2;
}

__global__ void k_fill(const int* __restrict__ uid, const int* __restrict__ iid) {
    int e = blockIdx.x * blockDim.x + threadIdx.x;
    if (e < NE) {
        int u  = uid[e];
        int it = NU + iid[e];
        int p = atomicAdd(&g_cursor[u], 1);
        g_adj[p] = it;
        int q = atomicAdd(&g_cursor[it], 1);
        g_adj[q] = u;
    }
}

// embA = concat(user_emb, item_emb); out = 0.25 * embA (layer-0 term of the mean)
__global__ void k_init(const float4* __restrict__ ue, const float4* __restrict__ ie,
                       float4* __restrict__ out) {
    int i = blockIdx.x * blockDim.x + threadIdx.x;
    const int TOT = NN * ED / 4;
    const int UB  = NU * ED / 4;
    if (i < TOT) {
        float4 v = (i < UB) ? __ldg(&ue[i]) : __ldg(&ie[i - UB]);
        ((float4*)g_embA)[i] = v;
        out[i] = make_float4(0.25f * v.x, 0.25f * v.y, 0.25f * v.z, 0.25f * v.w);
    }
}

// One warp per node: new[node] = dinv[node] * sum_{s in adj(node)} dinv[s] * emb_src[s]
// out[node] += 0.25 * new[node]; optionally write new[node] for the next layer.
template <int SRC /*0: A->B, 1: B->A*/, bool WRITE_NEXT>
__global__ void k_gather(float* __restrict__ out) {
    int gt   = blockIdx.x * blockDim.x + threadIdx.x;
    int node = gt >> 5;
    if (node >= NN) return;
    int lane = gt & 31;

    const float2* __restrict__ sv =
        (const float2*)(SRC == 0 ? (const float*)g_embA : (const float*)g_embB);
    float2* __restrict__ nv = (float2*)(SRC == 0 ? (float*)g_embB : (float*)g_embA);

    int beg = g_rowptr[node];
    int end = g_rowptr[node + 1];

    float ax = 0.0f, ay = 0.0f;
    for (int base = beg; base < end; base += 32) {
        int idx  = base + lane;
        int myid = (idx < end) ? g_adj[idx] : 0;
        int cnt  = min(32, end - base);
        #pragma unroll 4
        for (int k = 0; k < cnt; k++) {
            int   s = __shfl_sync(0xffffffffu, myid, k);
            float w = __ldg(&g_dinv[s]);
            float2 v = __ldg(&sv[s * 32 + lane]);
            ax += w * v.x;
            ay += w * v.y;
        }
    }

    float wd = g_dinv[node];
    ax *= wd;
    ay *= wd;

    int off = node * 32 + lane;
    if (WRITE_NEXT) nv[off] = make_float2(ax, ay);

    float2* ov = (float2*)out;
    float2 o = ov[off];
    o.x += 0.25f * ax;
    o.y += 0.25f * ay;
    ov[off] = o;
}

extern "C" void kernel_launch(void* const* d_in, const int* in_sizes, int n_in,
                              void* d_out, int out_size) {
    const float* ue  = (const float*)d_in[0];   // user_emb [200000,64]
    const float* ie  = (const float*)d_in[1];   // item_emb [100000,64]
    const int*   uid = (const int*)d_in[2];     // user_ids [1M]
    const int*   iid = (const int*)d_in[3];     // item_ids [1M]
    float*       out = (float*)d_out;           // [300000,64]

    const int T = 256;

    k_zero<<<(NN + T - 1) / T, T>>>();
    k_count<<<(NE + T - 1) / T, T>>>(uid, iid);
    k_scan1<<<NBLK, SCAN_B>>>();
    k_scan2<<<1, 512>>>();
    k_scan3<<<NBLK, SCAN_B>>>();
    k_fill<<<(NE + T - 1) / T, T>>>(uid, iid);
    k_init<<<(NN * ED / 4 + T - 1) / T, T>>>((const float4*)ue, (const float4*)ie,
                                             (float4*)out);

    dim3 g((NN * 32 + T - 1) / T);
    k_gather<0, true ><<<g, T>>>(out);   // layer 1: A -> B
    k_gather<1, true ><<<g, T>>>(out);   // layer 2: B -> A
    k_gather<0, false><<<g, T>>>(out);   // layer 3: A -> (acc only)
}

// round 2
// speedup vs baseline: 1.2486x; 1.2486x over previous
#include <cuda_runtime.h>

#define NU 200000
#define NI 100000
#define NN 300000
#define NE 1000000
#define NE2 2000000
#define SCAN_B 1024
#define NBLK ((NN + SCAN_B - 1) / SCAN_B)   // 293

// Scratch (device globals — no allocation allowed)
__device__ int    g_deg[NN];
__device__ int    g_rowptr[NN + 1];
__device__ int    g_cursor[NN];
__device__ int    g_adj[NE2];
__device__ float  g_dinv[NN];
__device__ float4 g_embA[NN * 16];   // pre-multiplied: dinv[n] * e_L[n]
__device__ float4 g_embB[NN * 16];
__device__ int    g_part[SCAN_B];

__global__ void k_zero() {
    int i = blockIdx.x * blockDim.x + threadIdx.x;
    if (i < NN) g_deg[i] = 0;
}

__global__ void k_count(const int* __restrict__ uid, const int* __restrict__ iid) {
    int e = blockIdx.x * blockDim.x + threadIdx.x;
    if (e < NE) {
        atomicAdd(&g_deg[uid[e]], 1);
        atomicAdd(&g_deg[NU + iid[e]], 1);
    }
}

// Block-local inclusive scan of degrees -> exclusive rowptr (local); totals to g_part.
__global__ void k_scan1() {
    __shared__ int s[SCAN_B];
    int i = blockIdx.x * SCAN_B + threadIdx.x;
    int v = (i < NN) ? g_deg[i] : 0;
    s[threadIdx.x] = v;
    __syncthreads();
    for (int off = 1; off < SCAN_B; off <<= 1) {
        int t = (threadIdx.x >= off) ? s[threadIdx.x - off] : 0;
        __syncthreads();
        s[threadIdx.x] += t;
        __syncthreads();
    }
    if (i < NN) g_rowptr[i] = s[threadIdx.x] - v;   // exclusive within block
    if (threadIdx.x == SCAN_B - 1) g_part[blockIdx.x] = s[SCAN_B - 1];
}

// Every block redundantly scans the 293 partials in smem, then applies its
// offset + finalizes rowptr/cursor/dinv. (Replaces the old scan2+scan3 pair.)
__global__ void k_scan23() {
    __shared__ int s[SCAN_B];
    int tid = threadIdx.x;
    int pv = (tid < NBLK) ? g_part[tid] : 0;
    s[tid] = pv;
    __syncthreads();
    for (int off = 1; off < SCAN_B; off <<= 1) {
        int t = (tid >= off) ? s[tid - off] : 0;
        __syncthreads();
        s[tid] += t;
        __syncthreads();
    }
    int boff = (blockIdx.x > 0) ? s[blockIdx.x - 1] : 0;   // exclusive block offset
    int i = blockIdx.x * SCAN_B + tid;
    if (i < NN) {
        int r = g_rowptr[i] + boff;
        g_rowptr[i] = r;
        g_cursor[i] = r;
        int d = g_deg[i];
        g_dinv[i] = (d > 0) ? rsqrtf((float)d) : 0.0f;
    }
    if (i == 0) g_rowptr[NN] = NE2;
}

// Fill adjacency (edge-parallel) + init P0 = dinv*e0 and out = 0.25*e0.
__global__ void k_fill_init(const int* __restrict__ uid, const int* __restrict__ iid,
                            const float4* __restrict__ ue, const float4* __restrict__ ie,
                            float4* __restrict__ out) {
    int t = blockIdx.x * blockDim.x + threadIdx.x;
    if (t < NE) {
        int u  = uid[t];
        int it = NU + iid[t];
        g_adj[atomicAdd(&g_cursor[u], 1)]  = it;
        g_adj[atomicAdd(&g_cursor[it], 1)] = u;
    }
    if (t < NN * 16) {
        float4 v = (t < NU * 16) ? __ldg(&ue[t]) : __ldg(&ie[t - NU * 16]);
        float di = g_dinv[t >> 4];
        g_embA[t] = make_float4(di * v.x, di * v.y, di * v.z, di * v.w);
        __stcs(&out[t], make_float4(0.25f * v.x, 0.25f * v.y, 0.25f * v.z, 0.25f * v.w));
    }
}

// Half-warp (16 lanes) per node, float4 per lane (one 256B row per neighbor).
// Source buffer holds P_L = dinv*e_L, so inner loop is pure adds:
//   sum = sum_{s in adj(node)} P_L[s]
//   e_{L+1}[node] = dinv[node]*sum ;  P_{L+1}[node] = dinv[node]^2 * sum
//   out[node] += 0.25 * dinv[node] * sum
template <int SRC /*0: A->B, 1: B->A*/, bool WRITE_NEXT>
__global__ void __launch_bounds__(256) k_gather(float4* __restrict__ out) {
    int gt   = blockIdx.x * blockDim.x + threadIdx.x;
    int node = gt >> 4;
    if (node >= NN) return;
    int lane = gt & 15;
    unsigned hmask = (threadIdx.x & 16) ? 0xFFFF0000u : 0x0000FFFFu;

    const float4* __restrict__ sv = (SRC == 0) ? g_embA : g_embB;
    float4*       __restrict__ nv = (SRC == 0) ? g_embB : g_embA;

    int beg = g_rowptr[node];
    int end = g_rowptr[node + 1];

    float ax = 0.f, ay = 0.f, az = 0.f, aw = 0.f;
    for (int base = beg; base < end; base += 16) {
        int idx  = base + lane;
        int myid = (idx < end) ? g_adj[idx] : 0;
        int cnt  = min(16, end - base);
        #pragma unroll 8
        for (int k = 0; k < cnt; k++) {
            int s = __shfl_sync(hmask, myid, k, 16);
            float4 v = __ldg(&sv[s * 16 + lane]);
            ax += v.x; ay += v.y; az += v.z; aw += v.w;
        }
    }

    float wd  = g_dinv[node];
    int   off = node * 16 + lane;
    if (WRITE_NEXT) {
        float w2 = wd * wd;
        nv[off] = make_float4(w2 * ax, w2 * ay, w2 * az, w2 * aw);
    }
    float  q = 0.25f * wd;
    float4 o = __ldcs(&out[off]);
    o.x += q * ax; o.y += q * ay; o.z += q * az; o.w += q * aw;
    __stcs(&out[off], o);
}

extern "C" void kernel_launch(void* const* d_in, const int* in_sizes, int n_in,
                              void* d_out, int out_size) {
    const float* ue  = (const float*)d_in[0];   // user_emb [200000,64]
    const float* ie  = (const float*)d_in[1];   // item_emb [100000,64]
    const int*   uid = (const int*)d_in[2];     // user_ids [1M]
    const int*   iid = (const int*)d_in[3];     // item_ids [1M]
    float4*      out = (float4*)d_out;          // [300000,64]

    const int T = 256;

    k_zero  <<<(NN + T - 1) / T, T>>>();
    k_count <<<(NE + T - 1) / T, T>>>(uid, iid);
    k_scan1 <<<NBLK, SCAN_B>>>();
    k_scan23<<<NBLK, SCAN_B>>>();
    k_fill_init<<<(NN * 16 + T - 1) / T, T>>>(uid, iid, (const float4*)ue,
                                              (const float4*)ie, out);

    dim3 g((NN * 16 + T - 1) / T);
    k_gather<0, true ><<<g, T>>>(out);   // layer 1: A -> B   (profiled by -s 5)
    k_gather<1, true ><<<g, T>>>(out);   // layer 2: B -> A
    k_gather<0, false><<<g, T>>>(out);   // layer 3: A -> acc only
}